// round 4
// baseline (speedup 1.0000x reference)
#include <cuda_runtime.h>
#include <cuda_bf16.h>
#include <math.h>

// ---------------------------------------------------------------------------
// TransformerBlock for GB300 (sm_103a) — round 4
// GEMMs + attention on tensor cores (mma.sync m16n8k8 tf32), LN fp32 SIMT.
// Attention: 128-query tiles, 8 warps/block (halved K/V L2 traffic vs r3).
// B=4, S=2048, D_MODEL=1024, N_HEADS=16, HEAD_DIM=64, FF=4096
// ---------------------------------------------------------------------------

#define M_ROWS   8192          // B*S
#define DMODEL   1024
#define FFDIM    4096
#define NHEADS   16
#define HDIM     64
#define SEQ      2048
#define BATCH    4

// scratch (static device globals -- allocation is forbidden)
__device__ float g_q   [M_ROWS * DMODEL];
__device__ float g_k   [M_ROWS * DMODEL];
__device__ float g_v   [M_ROWS * DMODEL];
__device__ float g_attn[M_ROWS * DMODEL];
__device__ float g_x1  [M_ROWS * DMODEL];
__device__ float g_tmp [M_ROWS * DMODEL];
__device__ float g_h   [M_ROWS * FFDIM];

// ---------------------------------------------------------------------------
// tf32 helpers
// ---------------------------------------------------------------------------
__device__ __forceinline__ unsigned f2tf32(float f) {
    unsigned u;
    asm("cvt.rna.tf32.f32 %0, %1;" : "=r"(u) : "f"(f));
    return u;
}

__device__ __forceinline__ void mma_tf32(float4& c,
                                         unsigned a0, unsigned a1,
                                         unsigned a2, unsigned a3,
                                         unsigned b0, unsigned b1)
{
    asm volatile(
        "mma.sync.aligned.m16n8k8.row.col.f32.tf32.tf32.f32 "
        "{%0,%1,%2,%3}, {%4,%5,%6,%7}, {%8,%9}, {%0,%1,%2,%3};"
        : "+f"(c.x), "+f"(c.y), "+f"(c.z), "+f"(c.w)
        : "r"(a0), "r"(a1), "r"(a2), "r"(a3), "r"(b0), "r"(b1));
}

// ---------------------------------------------------------------------------
// GEMM: C[M,N] = A[M,K] @ B[N,K]^T + bias[N]   (torch Linear "NT")
// tf32 tensor cores. 128x128 block, BK=16, 256 threads (8 warps, 4x2 grid),
// warp tile 32x64 => 2 m-frags x 8 n-frags of m16n8k8.
// Smem: transposed [k][m] tiles, stride 136 (conflict-free loads & stores),
// double buffered. EPI: 0 = bias, 1 = bias + exact GELU.
// ---------------------------------------------------------------------------
#define GBM 128
#define GBN 128
#define GBK 16
#define GSTR 136   // padded m-stride in smem words; 136 % 32 == 8 -> conflict-free frag loads

template<int EPI>
__global__ __launch_bounds__(256)
void gemm_tc(const float* __restrict__ A, const float* __restrict__ B,
             const float* __restrict__ bias, float* __restrict__ C,
             int M, int N, int K)
{
    __shared__ unsigned As[2][GBK][GSTR];
    __shared__ unsigned Bs[2][GBK][GSTR];

    const int tid  = threadIdx.x;
    const int warp = tid >> 5;
    const int lane = tid & 31;
    const int gid  = lane >> 2;    // 0..7
    const int tig  = lane & 3;     // 0..3
    const int warp_m = warp & 3;   // 0..3
    const int warp_n = warp >> 2;  // 0..1

    const int brow = blockIdx.y * GBM;
    const int bcol = blockIdx.x * GBN;

    const int lrow = tid & 127;
    const int lk8  = (tid >> 7) * 8;      // 0 or 8

    const float* Ap = A + (size_t)(brow + lrow) * K + lk8;
    const float* Bp = B + (size_t)(bcol + lrow) * K + lk8;

    float4 acc[2][8];
    #pragma unroll
    for (int i = 0; i < 2; i++)
        #pragma unroll
        for (int j = 0; j < 8; j++)
            acc[i][j] = make_float4(0.f, 0.f, 0.f, 0.f);

    // prologue: load first k-tile
    float4 a40 = *(const float4*)(Ap);
    float4 a41 = *(const float4*)(Ap + 4);
    float4 b40 = *(const float4*)(Bp);
    float4 b41 = *(const float4*)(Bp + 4);
    int buf = 0;
    {
        const float* av = &a40.x;
        const float* bv = &b40.x;
        #pragma unroll
        for (int c = 0; c < 4; c++) {
            As[buf][lk8 + c][lrow]     = f2tf32(av[c]);
            As[buf][lk8 + 4 + c][lrow] = f2tf32((&a41.x)[c]);
            Bs[buf][lk8 + c][lrow]     = f2tf32(bv[c]);
            Bs[buf][lk8 + 4 + c][lrow] = f2tf32((&b41.x)[c]);
        }
    }
    __syncthreads();

    const int m0 = warp_m * 32;
    const int n0 = warp_n * 64;

    for (int k0 = GBK; k0 <= K; k0 += GBK) {
        const bool more = (k0 < K);
        if (more) {
            a40 = *(const float4*)(Ap + k0);
            a41 = *(const float4*)(Ap + k0 + 4);
            b40 = *(const float4*)(Bp + k0);
            b41 = *(const float4*)(Bp + k0 + 4);
        }

        #pragma unroll
        for (int ks = 0; ks < GBK; ks += 8) {
            unsigned af[2][4];
            #pragma unroll
            for (int mf = 0; mf < 2; mf++) {
                const int mrow = m0 + mf * 16 + gid;
                af[mf][0] = As[buf][ks + tig][mrow];
                af[mf][1] = As[buf][ks + tig][mrow + 8];
                af[mf][2] = As[buf][ks + tig + 4][mrow];
                af[mf][3] = As[buf][ks + tig + 4][mrow + 8];
            }
            unsigned bf[8][2];
            #pragma unroll
            for (int nf = 0; nf < 8; nf++) {
                const int ncol = n0 + nf * 8 + gid;
                bf[nf][0] = Bs[buf][ks + tig][ncol];
                bf[nf][1] = Bs[buf][ks + tig + 4][ncol];
            }
            #pragma unroll
            for (int mf = 0; mf < 2; mf++)
                #pragma unroll
                for (int nf = 0; nf < 8; nf++)
                    mma_tf32(acc[mf][nf],
                             af[mf][0], af[mf][1], af[mf][2], af[mf][3],
                             bf[nf][0], bf[nf][1]);
        }

        if (more) {
            buf ^= 1;
            const float* av = &a40.x;
            const float* bv = &b40.x;
            #pragma unroll
            for (int c = 0; c < 4; c++) {
                As[buf][lk8 + c][lrow]     = f2tf32(av[c]);
                As[buf][lk8 + 4 + c][lrow] = f2tf32((&a41.x)[c]);
                Bs[buf][lk8 + c][lrow]     = f2tf32(bv[c]);
                Bs[buf][lk8 + 4 + c][lrow] = f2tf32((&b41.x)[c]);
            }
            __syncthreads();
        }
    }

    // epilogue: bias (+gelu), float2 stores
    #pragma unroll
    for (int mf = 0; mf < 2; mf++) {
        #pragma unroll
        for (int nf = 0; nf < 8; nf++) {
            const int mrow = brow + m0 + mf * 16 + gid;
            const int ncol = bcol + n0 + nf * 8 + tig * 2;
            const float bs0 = bias[ncol];
            const float bs1 = bias[ncol + 1];
            float v0 = acc[mf][nf].x + bs0;
            float v1 = acc[mf][nf].y + bs1;
            float v2 = acc[mf][nf].z + bs0;
            float v3 = acc[mf][nf].w + bs1;
            if (EPI == 1) {
                v0 = 0.5f * v0 * (1.0f + erff(v0 * 0.70710678118654752f));
                v1 = 0.5f * v1 * (1.0f + erff(v1 * 0.70710678118654752f));
                v2 = 0.5f * v2 * (1.0f + erff(v2 * 0.70710678118654752f));
                v3 = 0.5f * v3 * (1.0f + erff(v3 * 0.70710678118654752f));
            }
            *(float2*)&C[(size_t)mrow * N + ncol]       = make_float2(v0, v1);
            *(float2*)&C[(size_t)(mrow + 8) * N + ncol] = make_float2(v2, v3);
        }
    }
}

// ---------------------------------------------------------------------------
// Flash attention on tensor cores (tf32 mma, fp32 online softmax).
// grid (SEQ/128, B*H), 256 threads = 8 warps. Each warp owns 16 query rows.
// Key tiles of 64. HDIM = 64. One K/V tile load serves 128 queries.
//   S = Q K^T : A = Q (row-major [q][d]), B^T = K (row-major [key][d])
//   O += P V  : A = P (row-major [q][key]), B fragments read from V [key][d]
// Smem (dynamic, 70,656 B, tf32 bits):
//   Ks[64][68]  (stride 68: frag load bank = gid*4+tig, conflict-free)
//   Vs[64][72]  (stride 72: frag load bank = tig*8+gid, conflict-free)
//   Ps[8][16][68] warp-private P pads (also used to stage Q at start)
// ---------------------------------------------------------------------------
#define QTILE 128
#define KSTR 68
#define VSTR 72
#define PSTR 68
#define ATTN_SMEM_WORDS (64*KSTR + 64*VSTR + 8*16*PSTR)
#define ATTN_SMEM_BYTES (ATTN_SMEM_WORDS * 4)

__global__ __launch_bounds__(256)
void attn_tc(const float* __restrict__ Q, const float* __restrict__ Kg,
             const float* __restrict__ Vg, float* __restrict__ O)
{
    extern __shared__ unsigned sm[];
    unsigned* Ks = sm;
    unsigned* Vs = sm + 64 * KSTR;
    unsigned* Ps = sm + 64 * KSTR + 64 * VSTR + (threadIdx.x >> 5) * 16 * PSTR;

    const int qt = blockIdx.x;                // 0..15
    const int bh = blockIdx.y;                // 0..63
    const size_t base = (size_t)(bh >> 4) * SEQ * DMODEL + (size_t)(bh & 15) * HDIM;

    const int tid  = threadIdx.x;
    const int warp = tid >> 5;
    const int lane = tid & 31;
    const int gid  = lane >> 2;   // 0..7
    const int tig  = lane & 3;    // 0..3

    // ---- stage this warp's 16 Q rows into its P pad, scaled, tf32 ----
    {
        const int r  = lane >> 1;           // 0..15
        const int c0 = (lane & 1) * 32;
        const float* qp = Q + base + (size_t)(qt * QTILE + warp * 16 + r) * DMODEL + c0;
        #pragma unroll
        for (int i = 0; i < 8; i++) {
            float4 v = *(const float4*)(qp + i * 4);
            Ps[r * PSTR + c0 + i * 4 + 0] = f2tf32(v.x * 0.125f);
            Ps[r * PSTR + c0 + i * 4 + 1] = f2tf32(v.y * 0.125f);
            Ps[r * PSTR + c0 + i * 4 + 2] = f2tf32(v.z * 0.125f);
            Ps[r * PSTR + c0 + i * 4 + 3] = f2tf32(v.w * 0.125f);
        }
    }
    __syncwarp();

    // Q fragments: 8 k-chunks x 4 regs, held for the whole kernel
    unsigned qa[8][4];
    #pragma unroll
    for (int kc = 0; kc < 8; kc++) {
        qa[kc][0] = Ps[gid * PSTR + kc * 8 + tig];
        qa[kc][1] = Ps[(gid + 8) * PSTR + kc * 8 + tig];
        qa[kc][2] = Ps[gid * PSTR + kc * 8 + tig + 4];
        qa[kc][3] = Ps[(gid + 8) * PSTR + kc * 8 + tig + 4];
    }

    float4 oacc[8];
    #pragma unroll
    for (int nf = 0; nf < 8; nf++) oacc[nf] = make_float4(0.f, 0.f, 0.f, 0.f);
    float m0 = -INFINITY, m1 = -INFINITY, l0 = 0.f, l1 = 0.f;

    for (int kt = 0; kt < SEQ / 64; kt++) {
        __syncthreads();   // previous iteration done reading Ks/Vs

        // ---- load K and V tiles (64x64 each), convert to tf32 ----
        // 256 threads: r = tid>>2 (0..63), c0 = (tid&3)*16, 4 float4 each
        {
            const int r  = tid >> 2;
            const int c0 = (tid & 3) * 16;
            const float* kp = Kg + base + (size_t)(kt * 64 + r) * DMODEL + c0;
            const float* vp = Vg + base + (size_t)(kt * 64 + r) * DMODEL + c0;
            #pragma unroll
            for (int i = 0; i < 4; i++) {
                float4 kv = *(const float4*)(kp + i * 4);
                Ks[r * KSTR + c0 + i * 4 + 0] = f2tf32(kv.x);
                Ks[r * KSTR + c0 + i * 4 + 1] = f2tf32(kv.y);
                Ks[r * KSTR + c0 + i * 4 + 2] = f2tf32(kv.z);
                Ks[r * KSTR + c0 + i * 4 + 3] = f2tf32(kv.w);
                float4 vv = *(const float4*)(vp + i * 4);
                Vs[r * VSTR + c0 + i * 4 + 0] = f2tf32(vv.x);
                Vs[r * VSTR + c0 + i * 4 + 1] = f2tf32(vv.y);
                Vs[r * VSTR + c0 + i * 4 + 2] = f2tf32(vv.z);
                Vs[r * VSTR + c0 + i * 4 + 3] = f2tf32(vv.w);
            }
        }
        __syncthreads();

        // ---- S = Q K^T (pre-scaled) : 8 kc x 8 nf mmas ----
        float4 sacc[8];
        #pragma unroll
        for (int nf = 0; nf < 8; nf++) sacc[nf] = make_float4(0.f, 0.f, 0.f, 0.f);

        #pragma unroll
        for (int kc = 0; kc < 8; kc++) {
            #pragma unroll
            for (int nf = 0; nf < 8; nf++) {
                // B[k=d][n=key] col-major == K[key][d]; b0=(k=tig,n=gid)
                unsigned b0 = Ks[(nf * 8 + gid) * KSTR + kc * 8 + tig];
                unsigned b1 = Ks[(nf * 8 + gid) * KSTR + kc * 8 + tig + 4];
                mma_tf32(sacc[nf], qa[kc][0], qa[kc][1], qa[kc][2], qa[kc][3], b0, b1);
            }
        }

        // ---- online softmax; rows r0=gid, r1=gid+8; row group = 4 lanes ----
        float mx0 = -INFINITY, mx1 = -INFINITY;
        #pragma unroll
        for (int nf = 0; nf < 8; nf++) {
            mx0 = fmaxf(mx0, fmaxf(sacc[nf].x, sacc[nf].y));
            mx1 = fmaxf(mx1, fmaxf(sacc[nf].z, sacc[nf].w));
        }
        mx0 = fmaxf(mx0, __shfl_xor_sync(0xffffffffu, mx0, 1));
        mx0 = fmaxf(mx0, __shfl_xor_sync(0xffffffffu, mx0, 2));
        mx1 = fmaxf(mx1, __shfl_xor_sync(0xffffffffu, mx1, 1));
        mx1 = fmaxf(mx1, __shfl_xor_sync(0xffffffffu, mx1, 2));

        const float mn0 = fmaxf(m0, mx0);
        const float mn1 = fmaxf(m1, mx1);
        const float al0 = __expf(m0 - mn0);
        const float al1 = __expf(m1 - mn1);
        m0 = mn0; m1 = mn1;

        float s0 = 0.f, s1 = 0.f;
        #pragma unroll
        for (int nf = 0; nf < 8; nf++) {
            sacc[nf].x = __expf(sacc[nf].x - mn0);
            sacc[nf].y = __expf(sacc[nf].y - mn0);
            sacc[nf].z = __expf(sacc[nf].z - mn1);
            sacc[nf].w = __expf(sacc[nf].w - mn1);
            s0 += sacc[nf].x + sacc[nf].y;
            s1 += sacc[nf].z + sacc[nf].w;
        }
        s0 += __shfl_xor_sync(0xffffffffu, s0, 1);
        s0 += __shfl_xor_sync(0xffffffffu, s0, 2);
        s1 += __shfl_xor_sync(0xffffffffu, s1, 1);
        s1 += __shfl_xor_sync(0xffffffffu, s1, 2);
        l0 = l0 * al0 + s0;
        l1 = l1 * al1 + s1;

        #pragma unroll
        for (int nf = 0; nf < 8; nf++) {
            oacc[nf].x *= al0; oacc[nf].y *= al0;
            oacc[nf].z *= al1; oacc[nf].w *= al1;
        }

        // ---- write P (C-frag layout) to warp-private pad, tf32 ----
        #pragma unroll
        for (int nf = 0; nf < 8; nf++) {
            Ps[gid * PSTR + nf * 8 + tig * 2]           = f2tf32(sacc[nf].x);
            Ps[gid * PSTR + nf * 8 + tig * 2 + 1]       = f2tf32(sacc[nf].y);
            Ps[(gid + 8) * PSTR + nf * 8 + tig * 2]     = f2tf32(sacc[nf].z);
            Ps[(gid + 8) * PSTR + nf * 8 + tig * 2 + 1] = f2tf32(sacc[nf].w);
        }
        __syncwarp();

        // ---- O += P V : 8 kc (key chunks) x 8 nf (d chunks) mmas ----
        #pragma unroll
        for (int kc = 0; kc < 8; kc++) {
            unsigned pa0 = Ps[gid * PSTR + kc * 8 + tig];
            unsigned pa1 = Ps[(gid + 8) * PSTR + kc * 8 + tig];
            unsigned pa2 = Ps[gid * PSTR + kc * 8 + tig + 4];
            unsigned pa3 = Ps[(gid + 8) * PSTR + kc * 8 + tig + 4];
            #pragma unroll
            for (int nf = 0; nf < 8; nf++) {
                // B[k=key][n=d] col-major == V[key][d]; b0=(k=tig,n=gid)
                unsigned b0 = Vs[(kc * 8 + tig) * VSTR + nf * 8 + gid];
                unsigned b1 = Vs[(kc * 8 + tig + 4) * VSTR + nf * 8 + gid];
                mma_tf32(oacc[nf], pa0, pa1, pa2, pa3, b0, b1);
            }
        }
        __syncwarp();   // P pad reads done before next iteration overwrites
    }

    // ---- normalize and write out ----
    const float inv0 = 1.0f / l0;
    const float inv1 = 1.0f / l1;
    const int row0 = qt * QTILE + warp * 16 + gid;
    #pragma unroll
    for (int nf = 0; nf < 8; nf++) {
        const int d = nf * 8 + tig * 2;
        *(float2*)&O[base + (size_t)row0 * DMODEL + d] =
            make_float2(oacc[nf].x * inv0, oacc[nf].y * inv0);
        *(float2*)&O[base + (size_t)(row0 + 8) * DMODEL + d] =
            make_float2(oacc[nf].z * inv1, oacc[nf].w * inv1);
    }
}

// ---------------------------------------------------------------------------
// residual add + LayerNorm: out = LN(x + y) * g + beta.  One block per row.
// ---------------------------------------------------------------------------
__global__ __launch_bounds__(256)
void add_ln_kernel(const float* __restrict__ X, const float* __restrict__ Y,
                   const float* __restrict__ g, const float* __restrict__ beta,
                   float* __restrict__ out)
{
    const int row = blockIdx.x;
    const int t = threadIdx.x;
    const size_t off = (size_t)row * DMODEL + t * 4;

    float4 xv = *(const float4*)&X[off];
    float4 yv = *(const float4*)&Y[off];
    float v0 = xv.x + yv.x, v1 = xv.y + yv.y, v2 = xv.z + yv.z, v3 = xv.w + yv.w;

    float s  = v0 + v1 + v2 + v3;
    float ss = v0 * v0 + v1 * v1 + v2 * v2 + v3 * v3;

    #pragma unroll
    for (int o2 = 16; o2 > 0; o2 >>= 1) {
        s  += __shfl_xor_sync(0xffffffffu, s,  o2);
        ss += __shfl_xor_sync(0xffffffffu, ss, o2);
    }
    __shared__ float red[16];
    const int w = t >> 5, lane = t & 31;
    if (lane == 0) { red[w] = s; red[8 + w] = ss; }
    __syncthreads();
    float S = 0.f, SS = 0.f;
    #pragma unroll
    for (int i = 0; i < 8; i++) { S += red[i]; SS += red[8 + i]; }

    const float mean = S * (1.0f / DMODEL);
    const float var  = SS * (1.0f / DMODEL) - mean * mean;
    const float rstd = rsqrtf(var + 1e-5f);

    float4 gv = *(const float4*)&g[t * 4];
    float4 bv = *(const float4*)&beta[t * 4];
    float4 r;
    r.x = (v0 - mean) * rstd * gv.x + bv.x;
    r.y = (v1 - mean) * rstd * gv.y + bv.y;
    r.z = (v2 - mean) * rstd * gv.z + bv.z;
    r.w = (v3 - mean) * rstd * gv.w + bv.w;
    *(float4*)&out[off] = r;
}

// ---------------------------------------------------------------------------
extern "C" void kernel_launch(void* const* d_in, const int* in_sizes, int n_in,
                              void* d_out, int out_size)
{
    const float* x     = (const float*)d_in[0];
    const float* wq    = (const float*)d_in[1];
    const float* bq    = (const float*)d_in[2];
    const float* wk    = (const float*)d_in[3];
    const float* bk    = (const float*)d_in[4];
    const float* wv    = (const float*)d_in[5];
    const float* bv    = (const float*)d_in[6];
    const float* wo    = (const float*)d_in[7];
    const float* bo    = (const float*)d_in[8];
    const float* w1    = (const float*)d_in[9];
    const float* b1    = (const float*)d_in[10];
    const float* w2    = (const float*)d_in[11];
    const float* b2    = (const float*)d_in[12];
    const float* g1    = (const float*)d_in[13];
    const float* beta1 = (const float*)d_in[14];
    const float* g2    = (const float*)d_in[15];
    const float* beta2 = (const float*)d_in[16];
    float* out = (float*)d_out;

    float *q, *k, *v, *attn, *x1, *tmp, *hbuf;
    cudaGetSymbolAddress((void**)&q,    g_q);
    cudaGetSymbolAddress((void**)&k,    g_k);
    cudaGetSymbolAddress((void**)&v,    g_v);
    cudaGetSymbolAddress((void**)&attn, g_attn);
    cudaGetSymbolAddress((void**)&x1,   g_x1);
    cudaGetSymbolAddress((void**)&tmp,  g_tmp);
    cudaGetSymbolAddress((void**)&hbuf, g_h);

    cudaFuncSetAttribute(attn_tc,
                         cudaFuncAttributeMaxDynamicSharedMemorySize,
                         ATTN_SMEM_BYTES);

    const dim3 thr(256);
    const dim3 gD(DMODEL / GBN, M_ROWS / GBM);   // (8, 64)
    const dim3 gF(FFDIM  / GBN, M_ROWS / GBM);   // (32, 64)

    // QKV projections
    gemm_tc<0><<<gD, thr>>>(x, wq, bq, q, M_ROWS, DMODEL, DMODEL);
    gemm_tc<0><<<gD, thr>>>(x, wk, bk, k, M_ROWS, DMODEL, DMODEL);
    gemm_tc<0><<<gD, thr>>>(x, wv, bv, v, M_ROWS, DMODEL, DMODEL);

    // attention (tensor cores, 128-query tiles)
    attn_tc<<<dim3(SEQ / QTILE, BATCH * NHEADS), 256, ATTN_SMEM_BYTES>>>(q, k, v, attn);

    // output projection + residual LN
    gemm_tc<0><<<gD, thr>>>(attn, wo, bo, tmp, M_ROWS, DMODEL, DMODEL);
    add_ln_kernel<<<M_ROWS, thr>>>(x, tmp, g1, beta1, x1);

    // FFN
    gemm_tc<1><<<gF, thr>>>(x1, w1, b1, hbuf, M_ROWS, FFDIM, DMODEL);
    gemm_tc<0><<<gD, thr>>>(hbuf, w2, b2, tmp, M_ROWS, DMODEL, FFDIM);
    add_ln_kernel<<<M_ROWS, thr>>>(x1, tmp, g2, beta2, out);
}

// round 11
// speedup vs baseline: 1.2202x; 1.2202x over previous
#include <cuda_runtime.h>
#include <cuda_bf16.h>
#include <math.h>

// ---------------------------------------------------------------------------
// TransformerBlock for GB300 (sm_103a) — round 11 (resubmit of unbenched R9)
// GEMMs: tf32 mma.sync, 128x256 block, 8 warps, 64x64 warp tile (1.0 LDS/MMA),
//        natural-layout smem stride 20 (conflict-free frags), double buffered.
//        QKV fused into one launch via blockIdx.z (wave-packing).
// Attention: unchanged from round 4 (measured 600us).
// B=4, S=2048, D_MODEL=1024, N_HEADS=16, HEAD_DIM=64, FF=4096
// ---------------------------------------------------------------------------

#define M_ROWS   8192          // B*S
#define DMODEL   1024
#define FFDIM    4096
#define NHEADS   16
#define HDIM     64
#define SEQ      2048
#define BATCH    4

// scratch (static device globals -- allocation is forbidden)
__device__ float g_q   [M_ROWS * DMODEL];
__device__ float g_k   [M_ROWS * DMODEL];
__device__ float g_v   [M_ROWS * DMODEL];
__device__ float g_attn[M_ROWS * DMODEL];
__device__ float g_x1  [M_ROWS * DMODEL];
__device__ float g_tmp [M_ROWS * DMODEL];
__device__ float g_h   [M_ROWS * FFDIM];

// ---------------------------------------------------------------------------
// tf32 helpers
// ---------------------------------------------------------------------------
__device__ __forceinline__ unsigned f2tf32(float f) {
    unsigned u;
    asm("cvt.rna.tf32.f32 %0, %1;" : "=r"(u) : "f"(f));
    return u;
}

__device__ __forceinline__ void mma_tf32(float4& c,
                                         unsigned a0, unsigned a1,
                                         unsigned a2, unsigned a3,
                                         unsigned b0, unsigned b1)
{
    asm volatile(
        "mma.sync.aligned.m16n8k8.row.col.f32.tf32.tf32.f32 "
        "{%0,%1,%2,%3}, {%4,%5,%6,%7}, {%8,%9}, {%0,%1,%2,%3};"
        : "+f"(c.x), "+f"(c.y), "+f"(c.z), "+f"(c.w)
        : "r"(a0), "r"(a1), "r"(a2), "r"(a3), "r"(b0), "r"(b1));
}

// ---------------------------------------------------------------------------
// GEMM: C[M,N] = A[M,K] @ B[N,K]^T + bias[N]   (torch Linear "NT")
// 128x256 block, BK=16, 256 threads = 8 warps (2 m x 4 n), warp tile 64x64
// => per k8 step per warp: 4 m-frags x 8 n-frags = 32 mma, 32 LDS (1.0/MMA).
// Smem natural layout [row][k], stride 20 words; conflict-free frag loads.
// Double buffered with register prefetch. cvt.rna at fill.
// gemm_qkv variant: blockIdx.z selects {B,bias,C} (QKV fusion; A shared).
// EPI: 0 = bias, 1 = bias + exact GELU.
// ---------------------------------------------------------------------------
#define GBM 128
#define GBN 256
#define GBK 16
#define ASTR 20
#define AWORDS (GBM * ASTR)   // 2560
#define BWORDS (GBN * ASTR)   // 5120
#define GEMM_SMEM_BYTES ((2 * AWORDS + 2 * BWORDS) * 4)   // 61440

template<int EPI>
__device__ __forceinline__
void gemm_body(const float* __restrict__ A, const float* __restrict__ B,
               const float* __restrict__ bias, float* __restrict__ C,
               int M, int N, int K)
{
    extern __shared__ unsigned smemu[];
    unsigned* AsBase = smemu;               // [2][AWORDS]
    unsigned* BsBase = smemu + 2 * AWORDS;  // [2][BWORDS]

    const int tid  = threadIdx.x;
    const int warp = tid >> 5;
    const int lane = tid & 31;
    const int gid  = lane >> 2;    // 0..7
    const int tig  = lane & 3;     // 0..3
    const int m0   = (warp & 1) * 64;   // warp m offset
    const int n0   = (warp >> 1) * 64;  // warp n offset

    const int brow = blockIdx.y * GBM;
    const int bcol = blockIdx.x * GBN;

    // fill assignment:
    //   A: thread t -> row t>>1, k-cols (t&1)*8 .. +8   (8 floats, 32B gmem)
    //   B: thread t -> row t, k-cols 0..16              (16 floats, 64B gmem)
    const int arow = tid >> 1;
    const int ak0  = (tid & 1) * 8;
    const float* Ap = A + (size_t)(brow + arow) * K + ak0;
    const float* Bp = B + (size_t)(bcol + tid) * K;

    float4 acc[4][8];
    #pragma unroll
    for (int i = 0; i < 4; i++)
        #pragma unroll
        for (int j = 0; j < 8; j++)
            acc[i][j] = make_float4(0.f, 0.f, 0.f, 0.f);

    // prologue: load + convert + store first k-tile
    float4 pa0 = *(const float4*)(Ap);
    float4 pa1 = *(const float4*)(Ap + 4);
    float4 pb0 = *(const float4*)(Bp);
    float4 pb1 = *(const float4*)(Bp + 4);
    float4 pb2 = *(const float4*)(Bp + 8);
    float4 pb3 = *(const float4*)(Bp + 12);

    int buf = 0;
    {
        unsigned* As = AsBase;
        unsigned* Bs = BsBase;
        const float* a0p = &pa0.x;
        const float* a1p = &pa1.x;
        #pragma unroll
        for (int c = 0; c < 4; c++) {
            As[arow * ASTR + ak0 + c]     = f2tf32(a0p[c]);
            As[arow * ASTR + ak0 + 4 + c] = f2tf32(a1p[c]);
        }
        const float* bp[4] = {&pb0.x, &pb1.x, &pb2.x, &pb3.x};
        #pragma unroll
        for (int q = 0; q < 4; q++)
            #pragma unroll
            for (int c = 0; c < 4; c++)
                Bs[tid * ASTR + q * 4 + c] = f2tf32(bp[q][c]);
    }
    __syncthreads();

    for (int k0 = GBK; k0 <= K; k0 += GBK) {
        const bool more = (k0 < K);
        if (more) {
            pa0 = *(const float4*)(Ap + k0);
            pa1 = *(const float4*)(Ap + k0 + 4);
            pb0 = *(const float4*)(Bp + k0);
            pb1 = *(const float4*)(Bp + k0 + 4);
            pb2 = *(const float4*)(Bp + k0 + 8);
            pb3 = *(const float4*)(Bp + k0 + 12);
        }

        const unsigned* As = AsBase + buf * AWORDS;
        const unsigned* Bs = BsBase + buf * BWORDS;

        #pragma unroll
        for (int ks = 0; ks < GBK; ks += 8) {
            unsigned af[4][4];
            #pragma unroll
            for (int mf = 0; mf < 4; mf++) {
                const int r = m0 + mf * 16 + gid;
                af[mf][0] = As[r * ASTR + ks + tig];
                af[mf][1] = As[(r + 8) * ASTR + ks + tig];
                af[mf][2] = As[r * ASTR + ks + tig + 4];
                af[mf][3] = As[(r + 8) * ASTR + ks + tig + 4];
            }
            unsigned bf[8][2];
            #pragma unroll
            for (int nf = 0; nf < 8; nf++) {
                const int r = n0 + nf * 8 + gid;
                bf[nf][0] = Bs[r * ASTR + ks + tig];
                bf[nf][1] = Bs[r * ASTR + ks + tig + 4];
            }
            #pragma unroll
            for (int mf = 0; mf < 4; mf++)
                #pragma unroll
                for (int nf = 0; nf < 8; nf++)
                    mma_tf32(acc[mf][nf],
                             af[mf][0], af[mf][1], af[mf][2], af[mf][3],
                             bf[nf][0], bf[nf][1]);
        }

        if (more) {
            buf ^= 1;
            unsigned* Asw = AsBase + buf * AWORDS;
            unsigned* Bsw = BsBase + buf * BWORDS;
            const float* a0p = &pa0.x;
            const float* a1p = &pa1.x;
            #pragma unroll
            for (int c = 0; c < 4; c++) {
                Asw[arow * ASTR + ak0 + c]     = f2tf32(a0p[c]);
                Asw[arow * ASTR + ak0 + 4 + c] = f2tf32(a1p[c]);
            }
            const float* bp[4] = {&pb0.x, &pb1.x, &pb2.x, &pb3.x};
            #pragma unroll
            for (int q = 0; q < 4; q++)
                #pragma unroll
                for (int c = 0; c < 4; c++)
                    Bsw[tid * ASTR + q * 4 + c] = f2tf32(bp[q][c]);
            __syncthreads();
        }
    }

    // epilogue: bias (+gelu), float2 stores
    #pragma unroll
    for (int mf = 0; mf < 4; mf++) {
        #pragma unroll
        for (int nf = 0; nf < 8; nf++) {
            const int mrow = brow + m0 + mf * 16 + gid;
            const int ncol = bcol + n0 + nf * 8 + tig * 2;
            const float bs0 = bias[ncol];
            const float bs1 = bias[ncol + 1];
            float v0 = acc[mf][nf].x + bs0;
            float v1 = acc[mf][nf].y + bs1;
            float v2 = acc[mf][nf].z + bs0;
            float v3 = acc[mf][nf].w + bs1;
            if (EPI == 1) {
                v0 = 0.5f * v0 * (1.0f + erff(v0 * 0.70710678118654752f));
                v1 = 0.5f * v1 * (1.0f + erff(v1 * 0.70710678118654752f));
                v2 = 0.5f * v2 * (1.0f + erff(v2 * 0.70710678118654752f));
                v3 = 0.5f * v3 * (1.0f + erff(v3 * 0.70710678118654752f));
            }
            *(float2*)&C[(size_t)mrow * N + ncol]       = make_float2(v0, v1);
            *(float2*)&C[(size_t)(mrow + 8) * N + ncol] = make_float2(v2, v3);
        }
    }
}

template<int EPI>
__global__ __launch_bounds__(256, 1)
void gemm_tc(const float* __restrict__ A, const float* __restrict__ B,
             const float* __restrict__ bias, float* __restrict__ C,
             int M, int N, int K)
{
    gemm_body<EPI>(A, B, bias, C, M, N, K);
}

// QKV fused: blockIdx.z in {0,1,2} selects weight/bias/output; A shared.
__global__ __launch_bounds__(256, 1)
void gemm_qkv(const float* __restrict__ A,
              const float* __restrict__ W0, const float* __restrict__ b0,
              float* __restrict__ C0,
              const float* __restrict__ W1, const float* __restrict__ b1,
              float* __restrict__ C1,
              const float* __restrict__ W2, const float* __restrict__ b2,
              float* __restrict__ C2,
              int M, int N, int K)
{
    const float* W;
    const float* bb;
    float* C;
    if (blockIdx.z == 0)      { W = W0; bb = b0; C = C0; }
    else if (blockIdx.z == 1) { W = W1; bb = b1; C = C1; }
    else                      { W = W2; bb = b2; C = C2; }
    gemm_body<0>(A, W, bb, C, M, N, K);
}

// ---------------------------------------------------------------------------
// Flash attention on tensor cores (tf32 mma, fp32 online softmax).
// grid (SEQ/128, B*H), 256 threads = 8 warps. Each warp owns 16 query rows.
// Key tiles of 64. HDIM = 64. One K/V tile load serves 128 queries.
// Smem (dynamic, 70,656 B, tf32 bits):
//   Ks[64][68]  Vs[64][72]  Ps[8][16][68] (warp-private; stages Q at start)
// ---------------------------------------------------------------------------
#define QTILE 128
#define KSTR 68
#define VSTR 72
#define PSTR 68
#define ATTN_SMEM_WORDS (64*KSTR + 64*VSTR + 8*16*PSTR)
#define ATTN_SMEM_BYTES (ATTN_SMEM_WORDS * 4)

__global__ __launch_bounds__(256)
void attn_tc(const float* __restrict__ Q, const float* __restrict__ Kg,
             const float* __restrict__ Vg, float* __restrict__ O)
{
    extern __shared__ unsigned sm[];
    unsigned* Ks = sm;
    unsigned* Vs = sm + 64 * KSTR;
    unsigned* Ps = sm + 64 * KSTR + 64 * VSTR + (threadIdx.x >> 5) * 16 * PSTR;

    const int qt = blockIdx.x;                // 0..15
    const int bh = blockIdx.y;                // 0..63
    const size_t base = (size_t)(bh >> 4) * SEQ * DMODEL + (size_t)(bh & 15) * HDIM;

    const int tid  = threadIdx.x;
    const int warp = tid >> 5;
    const int lane = tid & 31;
    const int gid  = lane >> 2;   // 0..7
    const int tig  = lane & 3;    // 0..3

    // ---- stage this warp's 16 Q rows into its P pad, scaled, tf32 ----
    {
        const int r  = lane >> 1;           // 0..15
        const int c0 = (lane & 1) * 32;
        const float* qp = Q + base + (size_t)(qt * QTILE + warp * 16 + r) * DMODEL + c0;
        #pragma unroll
        for (int i = 0; i < 8; i++) {
            float4 v = *(const float4*)(qp + i * 4);
            Ps[r * PSTR + c0 + i * 4 + 0] = f2tf32(v.x * 0.125f);
            Ps[r * PSTR + c0 + i * 4 + 1] = f2tf32(v.y * 0.125f);
            Ps[r * PSTR + c0 + i * 4 + 2] = f2tf32(v.z * 0.125f);
            Ps[r * PSTR + c0 + i * 4 + 3] = f2tf32(v.w * 0.125f);
        }
    }
    __syncwarp();

    // Q fragments: 8 k-chunks x 4 regs, held for the whole kernel
    unsigned qa[8][4];
    #pragma unroll
    for (int kc = 0; kc < 8; kc++) {
        qa[kc][0] = Ps[gid * PSTR + kc * 8 + tig];
        qa[kc][1] = Ps[(gid + 8) * PSTR + kc * 8 + tig];
        qa[kc][2] = Ps[gid * PSTR + kc * 8 + tig + 4];
        qa[kc][3] = Ps[(gid + 8) * PSTR + kc * 8 + tig + 4];
    }

    float4 oacc[8];
    #pragma unroll
    for (int nf = 0; nf < 8; nf++) oacc[nf] = make_float4(0.f, 0.f, 0.f, 0.f);
    float m0 = -INFINITY, m1 = -INFINITY, l0 = 0.f, l1 = 0.f;

    for (int kt = 0; kt < SEQ / 64; kt++) {
        __syncthreads();   // previous iteration done reading Ks/Vs

        // ---- load K and V tiles (64x64 each), convert to tf32 ----
        {
            const int r  = tid >> 2;
            const int c0 = (tid & 3) * 16;
            const float* kp = Kg + base + (size_t)(kt * 64 + r) * DMODEL + c0;
            const float* vp = Vg + base + (size_t)(kt * 64 + r) * DMODEL + c0;
            #pragma unroll
            for (int i = 0; i < 4; i++) {
                float4 kv = *(const float4*)(kp + i * 4);
                Ks[r * KSTR + c0 + i * 4 + 0] = f2tf32(kv.x);
                Ks[r * KSTR + c0 + i * 4 + 1] = f2tf32(kv.y);
                Ks[r * KSTR + c0 + i * 4 + 2] = f2tf32(kv.z);
                Ks[r * KSTR + c0 + i * 4 + 3] = f2tf32(kv.w);
                float4 vv = *(const float4*)(vp + i * 4);
                Vs[r * VSTR + c0 + i * 4 + 0] = f2tf32(vv.x);
                Vs[r * VSTR + c0 + i * 4 + 1] = f2tf32(vv.y);
                Vs[r * VSTR + c0 + i * 4 + 2] = f2tf32(vv.z);
                Vs[r * VSTR + c0 + i * 4 + 3] = f2tf32(vv.w);
            }
        }
        __syncthreads();

        // ---- S = Q K^T (pre-scaled) : 8 kc x 8 nf mmas ----
        float4 sacc[8];
        #pragma unroll
        for (int nf = 0; nf < 8; nf++) sacc[nf] = make_float4(0.f, 0.f, 0.f, 0.f);

        #pragma unroll
        for (int kc = 0; kc < 8; kc++) {
            #pragma unroll
            for (int nf = 0; nf < 8; nf++) {
                unsigned b0 = Ks[(nf * 8 + gid) * KSTR + kc * 8 + tig];
                unsigned b1 = Ks[(nf * 8 + gid) * KSTR + kc * 8 + tig + 4];
                mma_tf32(sacc[nf], qa[kc][0], qa[kc][1], qa[kc][2], qa[kc][3], b0, b1);
            }
        }

        // ---- online softmax; rows r0=gid, r1=gid+8; row group = 4 lanes ----
        float mx0 = -INFINITY, mx1 = -INFINITY;
        #pragma unroll
        for (int nf = 0; nf < 8; nf++) {
            mx0 = fmaxf(mx0, fmaxf(sacc[nf].x, sacc[nf].y));
            mx1 = fmaxf(mx1, fmaxf(sacc[nf].z, sacc[nf].w));
        }
        mx0 = fmaxf(mx0, __shfl_xor_sync(0xffffffffu, mx0, 1));
        mx0 = fmaxf(mx0, __shfl_xor_sync(0xffffffffu, mx0, 2));
        mx1 = fmaxf(mx1, __shfl_xor_sync(0xffffffffu, mx1, 1));
        mx1 = fmaxf(mx1, __shfl_xor_sync(0xffffffffu, mx1, 2));

        const float mn0 = fmaxf(m0, mx0);
        const float mn1 = fmaxf(m1, mx1);
        const float al0 = __expf(m0 - mn0);
        const float al1 = __expf(m1 - mn1);
        m0 = mn0; m1 = mn1;

        float s0 = 0.f, s1 = 0.f;
        #pragma unroll
        for (int nf = 0; nf < 8; nf++) {
            sacc[nf].x = __expf(sacc[nf].x - mn0);
            sacc[nf].y = __expf(sacc[nf].y - mn0);
            sacc[nf].z = __expf(sacc[nf].z - mn1);
            sacc[nf].w = __expf(sacc[nf].w - mn1);
            s0 += sacc[nf].x + sacc[nf].y;
            s1 += sacc[nf].z + sacc[nf].w;
        }
        s0 += __shfl_xor_sync(0xffffffffu, s0, 1);
        s0 += __shfl_xor_sync(0xffffffffu, s0, 2);
        s1 += __shfl_xor_sync(0xffffffffu, s1, 1);
        s1 += __shfl_xor_sync(0xffffffffu, s1, 2);
        l0 = l0 * al0 + s0;
        l1 = l1 * al1 + s1;

        #pragma unroll
        for (int nf = 0; nf < 8; nf++) {
            oacc[nf].x *= al0; oacc[nf].y *= al0;
            oacc[nf].z *= al1; oacc[nf].w *= al1;
        }

        // ---- write P (C-frag layout) to warp-private pad, tf32 ----
        #pragma unroll
        for (int nf = 0; nf < 8; nf++) {
            Ps[gid * PSTR + nf * 8 + tig * 2]           = f2tf32(sacc[nf].x);
            Ps[gid * PSTR + nf * 8 + tig * 2 + 1]       = f2tf32(sacc[nf].y);
            Ps[(gid + 8) * PSTR + nf * 8 + tig * 2]     = f2tf32(sacc[nf].z);
            Ps[(gid + 8) * PSTR + nf * 8 + tig * 2 + 1] = f2tf32(sacc[nf].w);
        }
        __syncwarp();

        // ---- O += P V : 8 kc (key chunks) x 8 nf (d chunks) mmas ----
        #pragma unroll
        for (int kc = 0; kc < 8; kc++) {
            unsigned pa0 = Ps[gid * PSTR + kc * 8 + tig];
            unsigned pa1 = Ps[(gid + 8) * PSTR + kc * 8 + tig];
            unsigned pa2 = Ps[gid * PSTR + kc * 8 + tig + 4];
            unsigned pa3 = Ps[(gid + 8) * PSTR + kc * 8 + tig + 4];
            #pragma unroll
            for (int nf = 0; nf < 8; nf++) {
                unsigned b0 = Vs[(kc * 8 + tig) * VSTR + nf * 8 + gid];
                unsigned b1 = Vs[(kc * 8 + tig + 4) * VSTR + nf * 8 + gid];
                mma_tf32(oacc[nf], pa0, pa1, pa2, pa3, b0, b1);
            }
        }
        __syncwarp();   // P pad reads done before next iteration overwrites
    }

    // ---- normalize and write out ----
    const float inv0 = 1.0f / l0;
    const float inv1 = 1.0f / l1;
    const int row0 = qt * QTILE + warp * 16 + gid;
    #pragma unroll
    for (int nf = 0; nf < 8; nf++) {
        const int d = nf * 8 + tig * 2;
        *(float2*)&O[base + (size_t)row0 * DMODEL + d] =
            make_float2(oacc[nf].x * inv0, oacc[nf].y * inv0);
        *(float2*)&O[base + (size_t)(row0 + 8) * DMODEL + d] =
            make_float2(oacc[nf].z * inv1, oacc[nf].w * inv1);
    }
}

// ---------------------------------------------------------------------------
// residual add + LayerNorm: out = LN(x + y) * g + beta.  One block per row.
// ---------------------------------------------------------------------------
__global__ __launch_bounds__(256)
void add_ln_kernel(const float* __restrict__ X, const float* __restrict__ Y,
                   const float* __restrict__ g, const float* __restrict__ beta,
                   float* __restrict__ out)
{
    const int row = blockIdx.x;
    const int t = threadIdx.x;
    const size_t off = (size_t)row * DMODEL + t * 4;

    float4 xv = *(const float4*)&X[off];
    float4 yv = *(const float4*)&Y[off];
    float v0 = xv.x + yv.x, v1 = xv.y + yv.y, v2 = xv.z + yv.z, v3 = xv.w + yv.w;

    float s  = v0 + v1 + v2 + v3;
    float ss = v0 * v0 + v1 * v1 + v2 * v2 + v3 * v3;

    #pragma unroll
    for (int o2 = 16; o2 > 0; o2 >>= 1) {
        s  += __shfl_xor_sync(0xffffffffu, s,  o2);
        ss += __shfl_xor_sync(0xffffffffu, ss, o2);
    }
    __shared__ float red[16];
    const int w = t >> 5, lane = t & 31;
    if (lane == 0) { red[w] = s; red[8 + w] = ss; }
    __syncthreads();
    float S = 0.f, SS = 0.f;
    #pragma unroll
    for (int i = 0; i < 8; i++) { S += red[i]; SS += red[8 + i]; }

    const float mean = S * (1.0f / DMODEL);
    const float var  = SS * (1.0f / DMODEL) - mean * mean;
    const float rstd = rsqrtf(var + 1e-5f);

    float4 gv = *(const float4*)&g[t * 4];
    float4 bv = *(const float4*)&beta[t * 4];
    float4 r;
    r.x = (v0 - mean) * rstd * gv.x + bv.x;
    r.y = (v1 - mean) * rstd * gv.y + bv.y;
    r.z = (v2 - mean) * rstd * gv.z + bv.z;
    r.w = (v3 - mean) * rstd * gv.w + bv.w;
    *(float4*)&out[off] = r;
}

// ---------------------------------------------------------------------------
extern "C" void kernel_launch(void* const* d_in, const int* in_sizes, int n_in,
                              void* d_out, int out_size)
{
    const float* x     = (const float*)d_in[0];
    const float* wq    = (const float*)d_in[1];
    const float* bq    = (const float*)d_in[2];
    const float* wk    = (const float*)d_in[3];
    const float* bk    = (const float*)d_in[4];
    const float* wv    = (const float*)d_in[5];
    const float* bv    = (const float*)d_in[6];
    const float* wo    = (const float*)d_in[7];
    const float* bo    = (const float*)d_in[8];
    const float* w1    = (const float*)d_in[9];
    const float* b1    = (const float*)d_in[10];
    const float* w2    = (const float*)d_in[11];
    const float* b2    = (const float*)d_in[12];
    const float* g1    = (const float*)d_in[13];
    const float* beta1 = (const float*)d_in[14];
    const float* g2    = (const float*)d_in[15];
    const float* beta2 = (const float*)d_in[16];
    float* out = (float*)d_out;

    float *q, *k, *v, *attn, *x1, *tmp, *hbuf;
    cudaGetSymbolAddress((void**)&q,    g_q);
    cudaGetSymbolAddress((void**)&k,    g_k);
    cudaGetSymbolAddress((void**)&v,    g_v);
    cudaGetSymbolAddress((void**)&attn, g_attn);
    cudaGetSymbolAddress((void**)&x1,   g_x1);
    cudaGetSymbolAddress((void**)&tmp,  g_tmp);
    cudaGetSymbolAddress((void**)&hbuf, g_h);

    cudaFuncSetAttribute(attn_tc,
                         cudaFuncAttributeMaxDynamicSharedMemorySize,
                         ATTN_SMEM_BYTES);
    cudaFuncSetAttribute(gemm_tc<0>,
                         cudaFuncAttributeMaxDynamicSharedMemorySize,
                         GEMM_SMEM_BYTES);
    cudaFuncSetAttribute(gemm_tc<1>,
                         cudaFuncAttributeMaxDynamicSharedMemorySize,
                         GEMM_SMEM_BYTES);
    cudaFuncSetAttribute(gemm_qkv,
                         cudaFuncAttributeMaxDynamicSharedMemorySize,
                         GEMM_SMEM_BYTES);

    const dim3 thr(256);
    const dim3 gD(DMODEL / GBN, M_ROWS / GBM);      // (4, 64)
    const dim3 gQKV(DMODEL / GBN, M_ROWS / GBM, 3); // (4, 64, 3)
    const dim3 gF(FFDIM  / GBN, M_ROWS / GBM);      // (16, 64)

    // QKV projections — fused into one launch (wave packing + shared-A L2 reuse)
    gemm_qkv<<<gQKV, thr, GEMM_SMEM_BYTES>>>(x, wq, bq, q, wk, bk, k, wv, bv, v,
                                             M_ROWS, DMODEL, DMODEL);

    // attention (tensor cores, 128-query tiles)
    attn_tc<<<dim3(SEQ / QTILE, BATCH * NHEADS), 256, ATTN_SMEM_BYTES>>>(q, k, v, attn);

    // output projection + residual LN
    gemm_tc<0><<<gD, thr, GEMM_SMEM_BYTES>>>(attn, wo, bo, tmp, M_ROWS, DMODEL, DMODEL);
    add_ln_kernel<<<M_ROWS, thr>>>(x, tmp, g1, beta1, x1);

    // FFN
    gemm_tc<1><<<gF, thr, GEMM_SMEM_BYTES>>>(x1, w1, b1, hbuf, M_ROWS, FFDIM, DMODEL);
    gemm_tc<0><<<gD, thr, GEMM_SMEM_BYTES>>>(hbuf, w2, b2, tmp, M_ROWS, DMODEL, FFDIM);
    add_ln_kernel<<<M_ROWS, thr>>>(x1, tmp, g2, beta2, out);
}